// round 13
// baseline (speedup 1.0000x reference)
#include <cuda_runtime.h>
#include <cstdint>
#include <math.h>

#define TOKENS 16384
#define DIM    2048
#define NEXP   8
#define RANK   16
#define NFEAT  128
#define NTMAX  192
#define PAD    36            // 16B-aligned rows, conflict-free (36%32==4)
#define XSTG   (128*PAD)
#define WSTG   (32*PAD)

// -------- device scratch --------
__device__ float g_W1c[NFEAT*DIM];
__device__ float g_B2[NEXP*DIM*RANK];
__device__ float g_part[4*TOKENS*NEXP];   // gate partials [split][tok][e]
__device__ int   g_pid[TOKENS], g_rank[TOKENS];
__device__ int   g_cnt[64], g_off[64];
__device__ int   g_idx[TOKENS];
__device__ int   g_tilepid[NTMAX], g_tilestart[NTMAX], g_tilelen[NTMAX];
__device__ float g_probs_fallback[TOKENS*NEXP];

// -------- helpers --------
__device__ __forceinline__ uint32_t f2tf(float f){
    uint32_t u; asm("cvt.rna.tf32.f32 %0, %1;" : "=r"(u) : "f"(f)); return u;
}
__device__ __forceinline__ float rndtf(float f){ return __uint_as_float(f2tf(f)); }
__device__ __forceinline__ void mma8(float c[4], const uint32_t a[4], const uint32_t b[2]){
    asm volatile(
      "mma.sync.aligned.m16n8k8.row.col.f32.tf32.tf32.f32 "
      "{%0,%1,%2,%3},{%4,%5,%6,%7},{%8,%9},{%0,%1,%2,%3};"
      : "+f"(c[0]), "+f"(c[1]), "+f"(c[2]), "+f"(c[3])
      : "r"(a[0]), "r"(a[1]), "r"(a[2]), "r"(a[3]), "r"(b[0]), "r"(b[1]));
}
__device__ __forceinline__ void cp16(void* s, const void* g){
    uint32_t sa = (uint32_t)__cvta_generic_to_shared(s);
    asm volatile("cp.async.cg.shared.global [%0], [%1], 16;" :: "r"(sa), "l"(g));
}
__device__ __forceinline__ void cp_commit(){ asm volatile("cp.async.commit_group;"); }
template<int N> __device__ __forceinline__ void cp_wait(){
    asm volatile("cp.async.wait_group %0;" :: "n"(N));
}
__device__ __forceinline__ float gelu_exact(float v){
    return 0.5f * v * (1.0f + erff(v * 0.70710678118654752f));
}

// ======= Kernel A: pack weights (tf32 rna) + zero pair counters =======
__global__ void pack_kernel(const float* __restrict__ Bm, const float* __restrict__ A){
    int t = blockIdx.x * blockDim.x + threadIdx.x;
    if (t < 64) g_cnt[t] = 0;
    if (t < NFEAT * DIM)          g_W1c[t] = rndtf(A[t]);
    else if (t < 2 * NFEAT * DIM) g_B2[t - NFEAT*DIM] = rndtf(Bm[t - NFEAT*DIM]);
}

// ======= Kernel B: gate main — K-split x4, partial dot products =======
// grid (256, 4): 64 tokens/CTA x 512-dim split. 512 thr, 16KB smem.
__global__ __launch_bounds__(512) void gate_main(
    const float* __restrict__ x, const float* __restrict__ W)
{
    __shared__ float Wsm[NEXP*512];
    const int split = blockIdx.y;
    const int sbase = split * 128;              // float4 units within a 512-f4 row
    {
        const float4* Wg = reinterpret_cast<const float4*>(W);
        float4* Ws4 = reinterpret_cast<float4*>(Wsm);
        #pragma unroll
        for (int i = threadIdx.x; i < NEXP*128; i += 512){
            int e = i >> 7, q = i & 127;
            Ws4[i] = Wg[e*512 + sbase + q];
        }
    }
    __syncthreads();

    int warp = threadIdx.x >> 5, lane = threadIdx.x & 31;
    int tok0 = (blockIdx.x * 16 + warp) * 4;
    const float4* x4 = reinterpret_cast<const float4*>(x);
    const float4* W4 = reinterpret_cast<const float4*>(Wsm);

    float acc[4][8];
    #pragma unroll
    for (int t = 0; t < 4; t++)
        #pragma unroll
        for (int e = 0; e < 8; e++) acc[t][e] = 0.f;

    #pragma unroll
    for (int ii = 0; ii < 4; ii++){
        int i = lane + ii*32;
        float4 xv[4];
        #pragma unroll
        for (int t = 0; t < 4; t++)
            xv[t] = x4[(size_t)(tok0 + t)*512 + sbase + i];
        #pragma unroll
        for (int e = 0; e < 8; e++){
            float4 w = W4[e*128 + i];
            #pragma unroll
            for (int t = 0; t < 4; t++)
                acc[t][e] += xv[t].x*w.x + xv[t].y*w.y + xv[t].z*w.z + xv[t].w*w.w;
        }
    }
    #pragma unroll
    for (int t = 0; t < 4; t++)
        #pragma unroll
        for (int e = 0; e < 8; e++){
            float v = acc[t][e];
            #pragma unroll
            for (int s = 16; s > 0; s >>= 1) v += __shfl_xor_sync(0xffffffffu, v, s);
            acc[t][e] = v;
        }
    if (lane < 4){
        int tok = tok0 + lane;
        #pragma unroll
        for (int e = 0; e < 8; e++)
            g_part[((size_t)split*TOKENS + tok)*8 + e] = acc[lane][e];
    }
}

// ======= Kernel C: finalize — sum partials (fixed order), softmax, top2, rank =======
__global__ __launch_bounds__(256) void gate_fin(
    const float* __restrict__ bias, float* __restrict__ probs)
{
    int tok = blockIdx.x * blockDim.x + threadIdx.x;
    if (tok >= TOKENS) return;
    float lg[8];
    #pragma unroll
    for (int e = 0; e < 8; e++) lg[e] = bias[e];
    #pragma unroll
    for (int s = 0; s < 4; s++){
        const float4* p = reinterpret_cast<const float4*>(
            g_part + ((size_t)s*TOKENS + tok)*8);
        float4 a = p[0], b = p[1];
        lg[0]+=a.x; lg[1]+=a.y; lg[2]+=a.z; lg[3]+=a.w;
        lg[4]+=b.x; lg[5]+=b.y; lg[6]+=b.z; lg[7]+=b.w;
    }
    float mx = lg[0];
    #pragma unroll
    for (int e = 1; e < 8; e++) mx = fmaxf(mx, lg[e]);
    float p[8], s = 0.f;
    #pragma unroll
    for (int e = 0; e < 8; e++){ p[e] = expf(lg[e] - mx); s += p[e]; }
    float inv = 1.f / s;
    float4* pr = reinterpret_cast<float4*>(probs + (size_t)tok*8);
    pr[0] = make_float4(p[0]*inv, p[1]*inv, p[2]*inv, p[3]*inv);
    pr[1] = make_float4(p[4]*inv, p[5]*inv, p[6]*inv, p[7]*inv);
    // top-2 (lowest index wins ties, matching jax top_k)
    int i1 = 0;
    #pragma unroll
    for (int e = 1; e < 8; e++) if (lg[e] > lg[i1]) i1 = e;
    int i2 = (i1 == 0) ? 1 : 0;
    #pragma unroll
    for (int e = 0; e < 8; e++) if (e != i1 && lg[e] > lg[i2]) i2 = e;
    int lo = min(i1, i2), hi = max(i1, i2);
    int pid = lo*8 + hi;
    g_pid[tok]  = pid;
    g_rank[tok] = atomicAdd(&g_cnt[pid], 1);
}

// ======= Kernel D: scan + tile list (smem-based, no serial DRAM chain) =======
__global__ void scan_kernel(){
    __shared__ int c[64], o[64];
    int t = threadIdx.x;
    if (t < 64) c[t] = g_cnt[t];
    __syncthreads();
    if (t == 0){
        int off = 0;
        for (int b = 0; b < 64; b++){ o[b] = off; off += c[b]; }
    }
    __syncthreads();
    if (t < 64) g_off[t] = o[t];
    if (t == 0){
        int n = 0;
        for (int b = 0; b < 64; b++){
            int cc = c[b], s = o[b];
            while (cc > 0){
                g_tilepid[n] = b; g_tilestart[n] = s;
                g_tilelen[n] = (cc < 128) ? cc : 128;
                s += 128; cc -= 128; n++;
            }
        }
        for (; n < NTMAX; n++) g_tilelen[n] = 0;
    }
}

// ======= Kernel E: scatter (atomic-free) =======
__global__ void scatter_kernel(){
    int tok = blockIdx.x * blockDim.x + threadIdx.x;
    if (tok < TOKENS)
        g_idx[g_off[g_pid[tok]] + g_rank[tok]] = tok;
}

// ========= Kernel F: sparse fused GEMM1(K=2048,N=32) -> gelu -> GEMM2(K=32) =========
__global__ __launch_bounds__(256, 2) void fused_kernel(
    const float* __restrict__ x, float* __restrict__ out)
{
    const int len = g_tilelen[blockIdx.x];
    if (len == 0) return;
    const int start = g_tilestart[blockIdx.x];
    const int pid   = g_tilepid[blockIdx.x];
    const int e1 = pid >> 3, e2 = pid & 7;

    extern __shared__ float sm[];
    float* Xs  = sm;                       // 3 * 4608
    float* Ws  = Xs + 3*XSTG;              // 3 * 1152
    float* Hs  = Ws + 3*WSTG;              // 4608
    float* Bs  = Hs + 128*PAD;             // 2 * 2304
    int*   idx = reinterpret_cast<int*>(Bs + 2*64*PAD);   // 128

    const int tid  = threadIdx.x;
    const int warp = tid >> 5, lane = tid & 31;
    const int g = lane >> 2, t4 = lane & 3;
    const int mw = warp & 3, nw = warp >> 2;

    if (tid < 128){
        int r = (tid < len) ? tid : (len - 1);
        idx[tid] = g_idx[start + r];
    }
    __syncthreads();

    float acc[2][2][4];
    #pragma unroll
    for (int mf = 0; mf < 2; mf++)
        #pragma unroll
        for (int nf = 0; nf < 2; nf++)
            #pragma unroll
            for (int k = 0; k < 4; k++) acc[mf][nf][k] = 0.f;

    const int wf  = tid >> 3;
    const int gf  = (wf < 16) ? (e1*16 + wf) : (e2*16 + wf - 16);
    const int wc4 = tid & 7;
    const float* wsrc = g_W1c + (size_t)gf * DIM + wc4*4;

    auto loadStage = [&](int s){
        int st = (s % 3);
        int kb = s * 32;
        #pragma unroll
        for (int i = 0; i < 4; i++){
            int q = tid + i*256; int row = q >> 3; int c4 = q & 7;
            cp16(&Xs[st*XSTG + row*PAD + c4*4],
                 x + (size_t)idx[row]*DIM + kb + c4*4);
        }
        cp16(&Ws[st*WSTG + wf*PAD + wc4*4], wsrc + kb);
        cp_commit();
    };

    loadStage(0); loadStage(1);

    // one sync per stage: wait -> sync(publish s, free s-1) -> prefetch(s+2) -> compute(s)
    for (int s = 0; s < 64; s++){
        if (s < 63) cp_wait<1>();
        else        cp_wait<0>();
        __syncthreads();
        if (s + 2 < 64) loadStage(s + 2);

        const float* Ab = Xs + (s % 3)*XSTG + mw*32*PAD;
        const float* Wb = Ws + (s % 3)*WSTG + nw*16*PAD;
        #pragma unroll
        for (int ks = 0; ks < 4; ks++){
            int kc = ks * 8;
            uint32_t a[2][4];
            #pragma unroll
            for (int mf = 0; mf < 2; mf++){
                a[mf][0] = f2tf(Ab[(mf*16 +     g)*PAD + kc + t4]);
                a[mf][1] = f2tf(Ab[(mf*16 + 8 + g)*PAD + kc + t4]);
                a[mf][2] = f2tf(Ab[(mf*16 +     g)*PAD + kc + t4 + 4]);
                a[mf][3] = f2tf(Ab[(mf*16 + 8 + g)*PAD + kc + t4 + 4]);
            }
            #pragma unroll
            for (int nf = 0; nf < 2; nf++){
                uint32_t b[2];
                b[0] = __float_as_uint(Wb[(nf*8 + g)*PAD + kc + t4]);
                b[1] = __float_as_uint(Wb[(nf*8 + g)*PAD + kc + t4 + 4]);
                #pragma unroll
                for (int mf = 0; mf < 2; mf++) mma8(acc[mf][nf], a[mf], b);
            }
        }
    }
    __syncthreads();   // all warps done reading last stages before Hs写 (Hs separate; this also orders epilogue)

    // ---- epilogue 1: H' = tf32(gelu(H)) -> Hs ----
    #pragma unroll
    for (int mf = 0; mf < 2; mf++){
        int r0 = mw*32 + mf*16 + g;
        #pragma unroll
        for (int nf = 0; nf < 2; nf++){
            int c0 = nw*16 + nf*8 + 2*t4;
            Hs[r0*PAD + c0]       = rndtf(gelu_exact(acc[mf][nf][0]));
            Hs[r0*PAD + c0 + 1]   = rndtf(gelu_exact(acc[mf][nf][1]));
            Hs[(r0+8)*PAD + c0]   = rndtf(gelu_exact(acc[mf][nf][2]));
            Hs[(r0+8)*PAD + c0+1] = rndtf(gelu_exact(acc[mf][nf][3]));
        }
    }
    __syncthreads();

    // ------ GEMM2: out = H' @ [B_e1;B_e2]^T, K=32, 32 chunks of 64 dims ------
    auto loadB = [&](int c){
        int buf = c & 1;
        int dBase = c * 64;
        #pragma unroll
        for (int i = 0; i < 2; i++){
            int q = tid + i*256;
            int d = q >> 3; int j4 = q & 7;
            const float* src = (j4 < 4)
                ? g_B2 + ((size_t)e1*DIM + dBase + d)*RANK + j4*4
                : g_B2 + ((size_t)e2*DIM + dBase + d)*RANK + (j4-4)*4;
            cp16(&Bs[buf*64*PAD + d*PAD + j4*4], src);
        }
        cp_commit();
    };

    loadB(0);

    for (int c = 0; c < 32; c++){
        if (c + 1 < 32){ loadB(c + 1); cp_wait<1>(); }
        else           { cp_wait<0>(); }
        __syncthreads();

        float acc2[2][4][4];
        #pragma unroll
        for (int mf = 0; mf < 2; mf++)
            #pragma unroll
            for (int nf = 0; nf < 4; nf++)
                #pragma unroll
                for (int k = 0; k < 4; k++) acc2[mf][nf][k] = 0.f;

        const float* Hb = Hs + mw*32*PAD;
        const float* Bb = Bs + (c & 1)*64*PAD + nw*32*PAD;
        #pragma unroll
        for (int ks = 0; ks < 4; ks++){
            int kc = ks * 8;
            uint32_t a[2][4];
            #pragma unroll
            for (int mf = 0; mf < 2; mf++){
                a[mf][0] = __float_as_uint(Hb[(mf*16 +     g)*PAD + kc + t4]);
                a[mf][1] = __float_as_uint(Hb[(mf*16 + 8 + g)*PAD + kc + t4]);
                a[mf][2] = __float_as_uint(Hb[(mf*16 +     g)*PAD + kc + t4 + 4]);
                a[mf][3] = __float_as_uint(Hb[(mf*16 + 8 + g)*PAD + kc + t4 + 4]);
            }
            #pragma unroll
            for (int nf = 0; nf < 4; nf++){
                uint32_t b[2];
                b[0] = __float_as_uint(Bb[(nf*8 + g)*PAD + kc + t4]);
                b[1] = __float_as_uint(Bb[(nf*8 + g)*PAD + kc + t4 + 4]);
                #pragma unroll
                for (int mf = 0; mf < 2; mf++) mma8(acc2[mf][nf], a[mf], b);
            }
        }

        int dBase = c * 64;
        #pragma unroll
        for (int mf = 0; mf < 2; mf++){
            int ra = mw*32 + mf*16 + g;
            int rb = ra + 8;
            size_t toka = (size_t)idx[ra]*DIM;
            size_t tokb = (size_t)idx[rb]*DIM;
            #pragma unroll
            for (int nf = 0; nf < 4; nf++){
                int c0 = dBase + nw*32 + nf*8 + 2*t4;
                if (ra < len)
                    *reinterpret_cast<float2*>(&out[toka + c0]) =
                        make_float2(acc2[mf][nf][0], acc2[mf][nf][1]);
                if (rb < len)
                    *reinterpret_cast<float2*>(&out[tokb + c0]) =
                        make_float2(acc2[mf][nf][2], acc2[mf][nf][3]);
            }
        }
        __syncthreads();
    }
}

// ============================ launch ============================
extern "C" void kernel_launch(void* const* d_in, const int* in_sizes, int n_in,
                              void* d_out, int out_size)
{
    const float* x  = (const float*)d_in[0];
    const float* gW = (const float*)d_in[1];
    const float* gb = (const float*)d_in[2];
    const float* A  = (const float*)d_in[3];
    const float* Bm = (const float*)d_in[4];

    float* out = (float*)d_out;
    float* probs = out + (size_t)TOKENS * DIM;
    if (out_size < TOKENS*DIM + TOKENS*NEXP){
        void* p = nullptr;
        cudaGetSymbolAddress(&p, g_probs_fallback);
        probs = (float*)p;
    }

    size_t fused_smem = (size_t)(3*XSTG + 3*WSTG + 128*PAD + 2*64*PAD) * sizeof(float)
                      + 128 * sizeof(int);
    cudaFuncSetAttribute(fused_kernel, cudaFuncAttributeMaxDynamicSharedMemorySize,
                         (int)fused_smem);

    pack_kernel<<<(2*NFEAT*DIM + 511)/512, 512>>>(Bm, A);
    dim3 gg(256, 4);
    gate_main<<<gg, 512>>>(x, gW);
    gate_fin<<<TOKENS/256, 256>>>(gb, probs);
    scan_kernel<<<1, 64>>>();
    scatter_kernel<<<TOKENS/256, 256>>>();
    fused_kernel<<<NTMAX, 256, fused_smem>>>(x, out);
}

// round 14
// speedup vs baseline: 1.0175x; 1.0175x over previous
#include <cuda_runtime.h>
#include <cstdint>
#include <math.h>

#define TOKENS 16384
#define DIM    2048
#define NEXP   8
#define RANK   16
#define NFEAT  128
#define NTMAX  192
#define PAD    36            // 16B-aligned rows, conflict-free (36%32==4)
#define XSTG   (128*PAD)
#define WSTG   (32*PAD)

// -------- device scratch --------
__device__ float g_W1c[NFEAT*DIM];
__device__ float g_B2[NEXP*DIM*RANK];
__device__ float g_part[4*TOKENS*NEXP];       // gate partials [split][tok][e]
__device__ unsigned char g_pid8[TOKENS];
__device__ int   g_cnt[64];
__device__ float g_probs_fallback[TOKENS*NEXP];

// -------- helpers --------
__device__ __forceinline__ uint32_t f2tf(float f){
    uint32_t u; asm("cvt.rna.tf32.f32 %0, %1;" : "=r"(u) : "f"(f)); return u;
}
__device__ __forceinline__ float rndtf(float f){ return __uint_as_float(f2tf(f)); }
__device__ __forceinline__ void mma8(float c[4], const uint32_t a[4], const uint32_t b[2]){
    asm volatile(
      "mma.sync.aligned.m16n8k8.row.col.f32.tf32.tf32.f32 "
      "{%0,%1,%2,%3},{%4,%5,%6,%7},{%8,%9},{%0,%1,%2,%3};"
      : "+f"(c[0]), "+f"(c[1]), "+f"(c[2]), "+f"(c[3])
      : "r"(a[0]), "r"(a[1]), "r"(a[2]), "r"(a[3]), "r"(b[0]), "r"(b[1]));
}
__device__ __forceinline__ void cp16(void* s, const void* g){
    uint32_t sa = (uint32_t)__cvta_generic_to_shared(s);
    asm volatile("cp.async.cg.shared.global [%0], [%1], 16;" :: "r"(sa), "l"(g));
}
__device__ __forceinline__ void cp_commit(){ asm volatile("cp.async.commit_group;"); }
template<int N> __device__ __forceinline__ void cp_wait(){
    asm volatile("cp.async.wait_group %0;" :: "n"(N));
}
__device__ __forceinline__ float gelu_exact(float v){
    return 0.5f * v * (1.0f + erff(v * 0.70710678118654752f));
}

// ======= Kernel 1: gate main (K-split x4) + weight pack + counter zero =======
// grid (256, 4), 512 thr. Each thread also packs exactly one weight element.
__global__ __launch_bounds__(512) void gate_main(
    const float* __restrict__ x, const float* __restrict__ W,
    const float* __restrict__ Bm, const float* __restrict__ A)
{
    // ---- folded pack (1024 blocks * 512 thr == 2*NFEAT*DIM elements) ----
    {
        int flat = (int)(blockIdx.y * gridDim.x + blockIdx.x) * 512 + threadIdx.x;
        if (flat < 64) g_cnt[flat] = 0;
        if (flat < NFEAT*DIM) g_W1c[flat] = rndtf(A[flat]);
        else                  g_B2[flat - NFEAT*DIM] = rndtf(Bm[flat - NFEAT*DIM]);
    }

    __shared__ float Wsm[NEXP*512];
    const int split = blockIdx.y;
    const int sbase = split * 128;              // float4 units
    {
        const float4* Wg = reinterpret_cast<const float4*>(W);
        float4* Ws4 = reinterpret_cast<float4*>(Wsm);
        #pragma unroll
        for (int i = threadIdx.x; i < NEXP*128; i += 512){
            int e = i >> 7, q = i & 127;
            Ws4[i] = Wg[e*512 + sbase + q];
        }
    }
    __syncthreads();

    int warp = threadIdx.x >> 5, lane = threadIdx.x & 31;
    int tok0 = (blockIdx.x * 16 + warp) * 4;
    const float4* x4 = reinterpret_cast<const float4*>(x);
    const float4* W4 = reinterpret_cast<const float4*>(Wsm);

    float acc[4][8];
    #pragma unroll
    for (int t = 0; t < 4; t++)
        #pragma unroll
        for (int e = 0; e < 8; e++) acc[t][e] = 0.f;

    #pragma unroll
    for (int ii = 0; ii < 4; ii++){
        int i = lane + ii*32;
        float4 xv[4];
        #pragma unroll
        for (int t = 0; t < 4; t++)
            xv[t] = x4[(size_t)(tok0 + t)*512 + sbase + i];
        #pragma unroll
        for (int e = 0; e < 8; e++){
            float4 w = W4[e*128 + i];
            #pragma unroll
            for (int t = 0; t < 4; t++)
                acc[t][e] += xv[t].x*w.x + xv[t].y*w.y + xv[t].z*w.z + xv[t].w*w.w;
        }
    }
    #pragma unroll
    for (int t = 0; t < 4; t++)
        #pragma unroll
        for (int e = 0; e < 8; e++){
            float v = acc[t][e];
            #pragma unroll
            for (int s = 16; s > 0; s >>= 1) v += __shfl_xor_sync(0xffffffffu, v, s);
            acc[t][e] = v;
        }
    if (lane < 4){
        int tok = tok0 + lane;
        #pragma unroll
        for (int e = 0; e < 8; e++)
            g_part[((size_t)split*TOKENS + tok)*8 + e] = acc[lane][e];
    }
}

// ======= Kernel 2: finalize — sum partials, softmax, top2, pid byte + histogram =======
__global__ __launch_bounds__(256) void gate_fin(
    const float* __restrict__ bias, float* __restrict__ probs)
{
    __shared__ int hist[64];
    if (threadIdx.x < 64) hist[threadIdx.x] = 0;
    __syncthreads();

    int tok = blockIdx.x * blockDim.x + threadIdx.x;
    float lg[8];
    #pragma unroll
    for (int e = 0; e < 8; e++) lg[e] = bias[e];
    #pragma unroll
    for (int s = 0; s < 4; s++){
        const float4* p = reinterpret_cast<const float4*>(
            g_part + ((size_t)s*TOKENS + tok)*8);
        float4 a = p[0], b = p[1];
        lg[0]+=a.x; lg[1]+=a.y; lg[2]+=a.z; lg[3]+=a.w;
        lg[4]+=b.x; lg[5]+=b.y; lg[6]+=b.z; lg[7]+=b.w;
    }
    float mx = lg[0];
    #pragma unroll
    for (int e = 1; e < 8; e++) mx = fmaxf(mx, lg[e]);
    float p[8], s = 0.f;
    #pragma unroll
    for (int e = 0; e < 8; e++){ p[e] = expf(lg[e] - mx); s += p[e]; }
    float inv = 1.f / s;
    float4* pr = reinterpret_cast<float4*>(probs + (size_t)tok*8);
    pr[0] = make_float4(p[0]*inv, p[1]*inv, p[2]*inv, p[3]*inv);
    pr[1] = make_float4(p[4]*inv, p[5]*inv, p[6]*inv, p[7]*inv);
    // top-2 (lowest index wins ties, matching jax top_k)
    int i1 = 0;
    #pragma unroll
    for (int e = 1; e < 8; e++) if (lg[e] > lg[i1]) i1 = e;
    int i2 = (i1 == 0) ? 1 : 0;
    #pragma unroll
    for (int e = 0; e < 8; e++) if (e != i1 && lg[e] > lg[i2]) i2 = e;
    int lo = min(i1, i2), hi = max(i1, i2);
    int pid = lo*8 + hi;
    g_pid8[tok] = (unsigned char)pid;
    atomicAdd(&hist[pid], 1);
    __syncthreads();
    if (threadIdx.x < 64 && hist[threadIdx.x])
        atomicAdd(&g_cnt[threadIdx.x], hist[threadIdx.x]);
}

// ========= Kernel 3: sparse fused — self-routing preamble + GEMM1 -> gelu -> GEMM2 =========
__global__ __launch_bounds__(256, 2) void fused_kernel(
    const float* __restrict__ x, float* __restrict__ out)
{
    extern __shared__ float sm[];
    float* Xs  = sm;                       // 3 * 4608
    float* Ws  = Xs + 3*XSTG;              // 3 * 1152
    float* Hs  = Ws + 3*WSTG;              // 4608
    float* Bs  = Hs + 128*PAD;             // 2 * 2304
    int*   idx = reinterpret_cast<int*>(Bs + 2*64*PAD);   // 128

    const int tid  = threadIdx.x;
    const int warp = tid >> 5, lane = tid & 31;
    const int g = lane >> 2, t4 = lane & 3;
    const int mw = warp & 3, nw = warp >> 2;

    // ---------- preamble A: derive this CTA's tile from the histogram ----------
    __shared__ int s_pid, s_boff, s_len;
    __shared__ int s_cnt[64];
    __shared__ int s_wsum[8];
    __shared__ int s_running;
    if (tid < 64) s_cnt[tid] = g_cnt[tid];
    if (tid == 0){ s_len = 0; s_running = 0; }
    if (tid < 128) idx[tid] = 0;
    __syncthreads();
    if (tid == 0){
        int tile = 0;
        #pragma unroll 1
        for (int b = 0; b < 64; b++){
            int c = s_cnt[b];
            int nt = (c + 127) >> 7;
            if ((int)blockIdx.x >= tile && (int)blockIdx.x < tile + nt){
                int k = blockIdx.x - tile;
                s_pid  = b;
                s_boff = k * 128;
                int rem = c - k*128;
                s_len  = (rem < 128) ? rem : 128;
            }
            tile += nt;
        }
    }
    __syncthreads();
    const int len = s_len;
    if (len == 0) return;
    const int myPid = s_pid, bOff = s_boff;
    const int e1 = myPid >> 3, e2 = myPid & 7;

    // ---------- preamble B: gather token list by stream compaction ----------
    {
        const uint32_t pid4 = (uint32_t)myPid * 0x01010101u;
        #pragma unroll 1
        for (int base = 0; base < TOKENS; base += 1024){
            uint32_t p4 = *reinterpret_cast<const uint32_t*>(g_pid8 + base + tid*4);
            uint32_t eq = __vcmpeq4(p4, pid4);
            int c0 = (eq >>  0) & 1, c1 = (eq >>  8) & 1;
            int c2 = (eq >> 16) & 1, c3 = (eq >> 24) & 1;
            int mycnt = c0 + c1 + c2 + c3;
            int pre = mycnt;
            #pragma unroll
            for (int sh = 1; sh < 32; sh <<= 1){
                int v = __shfl_up_sync(0xffffffffu, pre, sh);
                if (lane >= sh) pre += v;
            }
            if (lane == 31) s_wsum[warp] = pre;
            __syncthreads();
            int wbase = 0;
            #pragma unroll
            for (int w = 0; w < 8; w++) if (w < warp) wbase += s_wsum[w];
            int pos = s_running + wbase + pre - mycnt;
            int tok = base + tid*4;
            if (c0){ if (pos >= bOff && pos < bOff + len) idx[pos - bOff] = tok;     pos++; }
            if (c1){ if (pos >= bOff && pos < bOff + len) idx[pos - bOff] = tok + 1; pos++; }
            if (c2){ if (pos >= bOff && pos < bOff + len) idx[pos - bOff] = tok + 2; pos++; }
            if (c3){ if (pos >= bOff && pos < bOff + len) idx[pos - bOff] = tok + 3; }
            __syncthreads();
            if (tid == 0){
                int t = 0;
                #pragma unroll
                for (int w = 0; w < 8; w++) t += s_wsum[w];
                s_running += t;
            }
            __syncthreads();
        }
    }
    // idx[] published by final __syncthreads above

    // ---------------- GEMM1: H = Xg @ Wslice^T, K = 2048, 3-stage PF=2 ----------------
    float acc[2][2][4];
    #pragma unroll
    for (int mf = 0; mf < 2; mf++)
        #pragma unroll
        for (int nf = 0; nf < 2; nf++)
            #pragma unroll
            for (int k = 0; k < 4; k++) acc[mf][nf][k] = 0.f;

    const int wf  = tid >> 3;
    const int gf  = (wf < 16) ? (e1*16 + wf) : (e2*16 + wf - 16);
    const int wc4 = tid & 7;
    const float* wsrc = g_W1c + (size_t)gf * DIM + wc4*4;

    auto loadStage = [&](int s){
        int st = (s % 3);
        int kb = s * 32;
        #pragma unroll
        for (int i = 0; i < 4; i++){
            int q = tid + i*256; int row = q >> 3; int c4 = q & 7;
            cp16(&Xs[st*XSTG + row*PAD + c4*4],
                 x + (size_t)idx[row]*DIM + kb + c4*4);
        }
        cp16(&Ws[st*WSTG + wf*PAD + wc4*4], wsrc + kb);
        cp_commit();
    };

    loadStage(0); loadStage(1);

    for (int s = 0; s < 64; s++){
        if (s < 63) cp_wait<1>();
        else        cp_wait<0>();
        __syncthreads();
        if (s + 2 < 64) loadStage(s + 2);

        const float* Ab = Xs + (s % 3)*XSTG + mw*32*PAD;
        const float* Wb = Ws + (s % 3)*WSTG + nw*16*PAD;
        #pragma unroll
        for (int ks = 0; ks < 4; ks++){
            int kc = ks * 8;
            uint32_t a[2][4];
            #pragma unroll
            for (int mf = 0; mf < 2; mf++){
                a[mf][0] = f2tf(Ab[(mf*16 +     g)*PAD + kc + t4]);
                a[mf][1] = f2tf(Ab[(mf*16 + 8 + g)*PAD + kc + t4]);
                a[mf][2] = f2tf(Ab[(mf*16 +     g)*PAD + kc + t4 + 4]);
                a[mf][3] = f2tf(Ab[(mf*16 + 8 + g)*PAD + kc + t4 + 4]);
            }
            #pragma unroll
            for (int nf = 0; nf < 2; nf++){
                uint32_t b[2];
                b[0] = __float_as_uint(Wb[(nf*8 + g)*PAD + kc + t4]);
                b[1] = __float_as_uint(Wb[(nf*8 + g)*PAD + kc + t4 + 4]);
                #pragma unroll
                for (int mf = 0; mf < 2; mf++) mma8(acc[mf][nf], a[mf], b);
            }
        }
    }
    __syncthreads();

    // ---- epilogue 1: H' = tf32(gelu(H)) -> Hs ----
    #pragma unroll
    for (int mf = 0; mf < 2; mf++){
        int r0 = mw*32 + mf*16 + g;
        #pragma unroll
        for (int nf = 0; nf < 2; nf++){
            int c0 = nw*16 + nf*8 + 2*t4;
            Hs[r0*PAD + c0]       = rndtf(gelu_exact(acc[mf][nf][0]));
            Hs[r0*PAD + c0 + 1]   = rndtf(gelu_exact(acc[mf][nf][1]));
            Hs[(r0+8)*PAD + c0]   = rndtf(gelu_exact(acc[mf][nf][2]));
            Hs[(r0+8)*PAD + c0+1] = rndtf(gelu_exact(acc[mf][nf][3]));
        }
    }
    __syncthreads();

    // ------ GEMM2: out = H' @ [B_e1;B_e2]^T, K=32, 32 chunks of 64 dims ------
    auto loadB = [&](int c){
        int buf = c & 1;
        int dBase = c * 64;
        #pragma unroll
        for (int i = 0; i < 2; i++){
            int q = tid + i*256;
            int d = q >> 3; int j4 = q & 7;
            const float* src = (j4 < 4)
                ? g_B2 + ((size_t)e1*DIM + dBase + d)*RANK + j4*4
                : g_B2 + ((size_t)e2*DIM + dBase + d)*RANK + (j4-4)*4;
            cp16(&Bs[buf*64*PAD + d*PAD + j4*4], src);
        }
        cp_commit();
    };

    loadB(0);

    for (int c = 0; c < 32; c++){
        if (c + 1 < 32){ loadB(c + 1); cp_wait<1>(); }
        else           { cp_wait<0>(); }
        __syncthreads();

        float acc2[2][4][4];
        #pragma unroll
        for (int mf = 0; mf < 2; mf++)
            #pragma unroll
            for (int nf = 0; nf < 4; nf++)
                #pragma unroll
                for (int k = 0; k < 4; k++) acc2[mf][nf][k] = 0.f;

        const float* Hb = Hs + mw*32*PAD;
        const float* Bb = Bs + (c & 1)*64*PAD + nw*32*PAD;
        #pragma unroll
        for (int ks = 0; ks < 4; ks++){
            int kc = ks * 8;
            uint32_t a[2][4];
            #pragma unroll
            for (int mf = 0; mf < 2; mf++){
                a[mf][0] = __float_as_uint(Hb[(mf*16 +     g)*PAD + kc + t4]);
                a[mf][1] = __float_as_uint(Hb[(mf*16 + 8 + g)*PAD + kc + t4]);
                a[mf][2] = __float_as_uint(Hb[(mf*16 +     g)*PAD + kc + t4 + 4]);
                a[mf][3] = __float_as_uint(Hb[(mf*16 + 8 + g)*PAD + kc + t4 + 4]);
            }
            #pragma unroll
            for (int nf = 0; nf < 4; nf++){
                uint32_t b[2];
                b[0] = __float_as_uint(Bb[(nf*8 + g)*PAD + kc + t4]);
                b[1] = __float_as_uint(Bb[(nf*8 + g)*PAD + kc + t4 + 4]);
                #pragma unroll
                for (int mf = 0; mf < 2; mf++) mma8(acc2[mf][nf], a[mf], b);
            }
        }

        int dBase = c * 64;
        #pragma unroll
        for (int mf = 0; mf < 2; mf++){
            int ra = mw*32 + mf*16 + g;
            int rb = ra + 8;
            size_t toka = (size_t)idx[ra]*DIM;
            size_t tokb = (size_t)idx[rb]*DIM;
            #pragma unroll
            for (int nf = 0; nf < 4; nf++){
                int c0 = dBase + nw*32 + nf*8 + 2*t4;
                if (ra < len)
                    *reinterpret_cast<float2*>(&out[toka + c0]) =
                        make_float2(acc2[mf][nf][0], acc2[mf][nf][1]);
                if (rb < len)
                    *reinterpret_cast<float2*>(&out[tokb + c0]) =
                        make_float2(acc2[mf][nf][2], acc2[mf][nf][3]);
            }
        }
        __syncthreads();
    }
}

// ============================ launch ============================
extern "C" void kernel_launch(void* const* d_in, const int* in_sizes, int n_in,
                              void* d_out, int out_size)
{
    const float* x  = (const float*)d_in[0];
    const float* gW = (const float*)d_in[1];
    const float* gb = (const float*)d_in[2];
    const float* A  = (const float*)d_in[3];
    const float* Bm = (const float*)d_in[4];

    float* out = (float*)d_out;
    float* probs = out + (size_t)TOKENS * DIM;
    if (out_size < TOKENS*DIM + TOKENS*NEXP){
        void* p = nullptr;
        cudaGetSymbolAddress(&p, g_probs_fallback);
        probs = (float*)p;
    }

    size_t fused_smem = (size_t)(3*XSTG + 3*WSTG + 128*PAD + 2*64*PAD) * sizeof(float)
                      + 128 * sizeof(int);
    cudaFuncSetAttribute(fused_kernel, cudaFuncAttributeMaxDynamicSharedMemorySize,
                         (int)fused_smem);

    dim3 gg(256, 4);
    gate_main<<<gg, 512>>>(x, gW, Bm, A);
    gate_fin<<<TOKENS/256, 256>>>(gb, probs);
    fused_kernel<<<NTMAX, 256, fused_smem>>>(x, out);
}

// round 15
// speedup vs baseline: 1.0428x; 1.0249x over previous
#include <cuda_runtime.h>
#include <cstdint>
#include <math.h>

#define TOKENS 16384
#define DIM    2048
#define NEXP   8
#define RANK   16
#define NFEAT  128
#define NTMAX  192
#define PAD    36            // 16B-aligned rows, conflict-free (36%32==4)
#define XSTG   (128*PAD)
#define WSTG   (32*PAD)

// -------- device scratch --------
__device__ float g_W1c[NFEAT*DIM];
__device__ float g_B2[NEXP*DIM*RANK];
__device__ unsigned char g_pid8[TOKENS];
__device__ int   g_cnt[64];
__device__ float g_probs_fallback[TOKENS*NEXP];

// -------- helpers --------
__device__ __forceinline__ uint32_t f2tf(float f){
    uint32_t u; asm("cvt.rna.tf32.f32 %0, %1;" : "=r"(u) : "f"(f)); return u;
}
__device__ __forceinline__ float rndtf(float f){ return __uint_as_float(f2tf(f)); }
__device__ __forceinline__ void mma8(float c[4], const uint32_t a[4], const uint32_t b[2]){
    asm volatile(
      "mma.sync.aligned.m16n8k8.row.col.f32.tf32.tf32.f32 "
      "{%0,%1,%2,%3},{%4,%5,%6,%7},{%8,%9},{%0,%1,%2,%3};"
      : "+f"(c[0]), "+f"(c[1]), "+f"(c[2]), "+f"(c[3])
      : "r"(a[0]), "r"(a[1]), "r"(a[2]), "r"(a[3]), "r"(b[0]), "r"(b[1]));
}
__device__ __forceinline__ void cp16(void* s, const void* g){
    uint32_t sa = (uint32_t)__cvta_generic_to_shared(s);
    asm volatile("cp.async.cg.shared.global [%0], [%1], 16;" :: "r"(sa), "l"(g));
}
__device__ __forceinline__ void cp_commit(){ asm volatile("cp.async.commit_group;"); }
template<int N> __device__ __forceinline__ void cp_wait(){
    asm volatile("cp.async.wait_group %0;" :: "n"(N));
}
__device__ __forceinline__ float gelu_exact(float v){
    return 0.5f * v * (1.0f + erff(v * 0.70710678118654752f));
}

// ======= Kernel 1: pack weights (tf32 rna) + zero pair counters =======
__global__ void pack_kernel(const float* __restrict__ Bm, const float* __restrict__ A){
    int t = blockIdx.x * blockDim.x + threadIdx.x;
    if (t < 64) g_cnt[t] = 0;
    if (t < NFEAT * DIM)          g_W1c[t] = rndtf(A[t]);
    else if (t < 2 * NFEAT * DIM) g_B2[t - NFEAT*DIM] = rndtf(Bm[t - NFEAT*DIM]);
}

// ======= Kernel 2: gate (fp32 exact) — single pass, 2 CTAs/SM =======
// 512 thr, 2 tokens/warp -> 32 tokens/CTA, grid 512. W staged in SMEM (64KB).
__global__ __launch_bounds__(512, 2) void gate_kernel(
    const float* __restrict__ x, const float* __restrict__ W,
    const float* __restrict__ bias, float* __restrict__ probs)
{
    extern __shared__ float Wsm[];           // 8*2048 floats = 64KB dynamic
    __shared__ int hist[64];
    if (threadIdx.x < 64) hist[threadIdx.x] = 0;
    {
        const float4* Wg = reinterpret_cast<const float4*>(W);
        float4* Ws4 = reinterpret_cast<float4*>(Wsm);
        for (int i = threadIdx.x; i < NEXP*DIM/4; i += 512) Ws4[i] = Wg[i];
    }
    __syncthreads();

    int warp = threadIdx.x >> 5, lane = threadIdx.x & 31;
    int tok0 = (blockIdx.x * 16 + warp) * 2;
    const float4* x4 = reinterpret_cast<const float4*>(x);
    const float4* W4 = reinterpret_cast<const float4*>(Wsm);

    float acc[2][8];
    #pragma unroll
    for (int t = 0; t < 2; t++)
        #pragma unroll
        for (int e = 0; e < 8; e++) acc[t][e] = 0.f;

    #pragma unroll 2
    for (int i = lane; i < 512; i += 32){
        float4 xv0 = x4[(size_t)tok0 * 512 + i];
        float4 xv1 = x4[(size_t)(tok0 + 1) * 512 + i];
        #pragma unroll
        for (int e = 0; e < 8; e++){
            float4 w = W4[e * 512 + i];
            acc[0][e] += xv0.x*w.x + xv0.y*w.y + xv0.z*w.z + xv0.w*w.w;
            acc[1][e] += xv1.x*w.x + xv1.y*w.y + xv1.z*w.z + xv1.w*w.w;
        }
    }
    #pragma unroll
    for (int t = 0; t < 2; t++)
        #pragma unroll
        for (int e = 0; e < 8; e++){
            float v = acc[t][e];
            #pragma unroll
            for (int s = 16; s > 0; s >>= 1) v += __shfl_xor_sync(0xffffffffu, v, s);
            acc[t][e] = v;
        }
    if (lane < 2){
        int t = lane, tok = tok0 + t;
        float lg[8]; float mx = -1e30f;
        #pragma unroll
        for (int e = 0; e < 8; e++){ lg[e] = acc[t][e] + bias[e]; mx = fmaxf(mx, lg[e]); }
        float p[8]; float s = 0.f;
        #pragma unroll
        for (int e = 0; e < 8; e++){ p[e] = expf(lg[e] - mx); s += p[e]; }
        float inv = 1.f / s;
        float4* pr = reinterpret_cast<float4*>(probs + (size_t)tok*8);
        pr[0] = make_float4(p[0]*inv, p[1]*inv, p[2]*inv, p[3]*inv);
        pr[1] = make_float4(p[4]*inv, p[5]*inv, p[6]*inv, p[7]*inv);
        // top-2 (lowest index wins ties, matching jax top_k)
        int i1 = 0;
        #pragma unroll
        for (int e = 1; e < 8; e++) if (lg[e] > lg[i1]) i1 = e;
        int i2 = (i1 == 0) ? 1 : 0;
        #pragma unroll
        for (int e = 0; e < 8; e++) if (e != i1 && lg[e] > lg[i2]) i2 = e;
        int lo = min(i1, i2), hi = max(i1, i2);
        int pid = lo*8 + hi;
        g_pid8[tok] = (unsigned char)pid;
        atomicAdd(&hist[pid], 1);
    }
    __syncthreads();
    if (threadIdx.x < 64 && hist[threadIdx.x])
        atomicAdd(&g_cnt[threadIdx.x], hist[threadIdx.x]);
}

// ========= Kernel 3: sparse fused — self-routing preamble + GEMM1 -> gelu -> GEMM2 =========
__global__ __launch_bounds__(256, 2) void fused_kernel(
    const float* __restrict__ x, float* __restrict__ out)
{
    extern __shared__ float sm[];
    float* Xs  = sm;                       // 3 * 4608
    float* Ws  = Xs + 3*XSTG;              // 3 * 1152
    float* Hs  = Ws + 3*WSTG;              // 4608
    float* Bs  = Hs + 128*PAD;             // 2 * 2304
    int*   idx = reinterpret_cast<int*>(Bs + 2*64*PAD);   // 128

    const int tid  = threadIdx.x;
    const int warp = tid >> 5, lane = tid & 31;
    const int g = lane >> 2, t4 = lane & 3;
    const int mw = warp & 3, nw = warp >> 2;

    // ---------- preamble A: derive this CTA's tile from the histogram ----------
    __shared__ int s_pid, s_boff, s_len;
    __shared__ int s_cnt[64];
    __shared__ int s_wsum[8];
    __shared__ int s_running;
    if (tid < 64) s_cnt[tid] = g_cnt[tid];
    if (tid == 0){ s_len = 0; s_running = 0; }
    if (tid < 128) idx[tid] = 0;
    __syncthreads();
    if (tid == 0){
        int tile = 0;
        #pragma unroll 1
        for (int b = 0; b < 64; b++){
            int c = s_cnt[b];
            int nt = (c + 127) >> 7;
            if ((int)blockIdx.x >= tile && (int)blockIdx.x < tile + nt){
                int k = blockIdx.x - tile;
                s_pid  = b;
                s_boff = k * 128;
                int rem = c - k*128;
                s_len  = (rem < 128) ? rem : 128;
            }
            tile += nt;
        }
    }
    __syncthreads();
    const int len = s_len;
    if (len == 0) return;
    const int myPid = s_pid, bOff = s_boff;
    const int e1 = myPid >> 3, e2 = myPid & 7;

    // ---------- preamble B: gather token list by stream compaction ----------
    {
        const uint32_t pid4 = (uint32_t)myPid * 0x01010101u;
        #pragma unroll 1
        for (int base = 0; base < TOKENS; base += 1024){
            uint32_t p4 = *reinterpret_cast<const uint32_t*>(g_pid8 + base + tid*4);
            uint32_t eq = __vcmpeq4(p4, pid4);
            int c0 = (eq >>  0) & 1, c1 = (eq >>  8) & 1;
            int c2 = (eq >> 16) & 1, c3 = (eq >> 24) & 1;
            int mycnt = c0 + c1 + c2 + c3;
            int pre = mycnt;
            #pragma unroll
            for (int sh = 1; sh < 32; sh <<= 1){
                int v = __shfl_up_sync(0xffffffffu, pre, sh);
                if (lane >= sh) pre += v;
            }
            if (lane == 31) s_wsum[warp] = pre;
            __syncthreads();
            int wbase = 0;
            #pragma unroll
            for (int w = 0; w < 8; w++) if (w < warp) wbase += s_wsum[w];
            int pos = s_running + wbase + pre - mycnt;
            int tok = base + tid*4;
            if (c0){ if (pos >= bOff && pos < bOff + len) idx[pos - bOff] = tok;     pos++; }
            if (c1){ if (pos >= bOff && pos < bOff + len) idx[pos - bOff] = tok + 1; pos++; }
            if (c2){ if (pos >= bOff && pos < bOff + len) idx[pos - bOff] = tok + 2; pos++; }
            if (c3){ if (pos >= bOff && pos < bOff + len) idx[pos - bOff] = tok + 3; }
            __syncthreads();
            if (tid == 0){
                int t = 0;
                #pragma unroll
                for (int w = 0; w < 8; w++) t += s_wsum[w];
                s_running += t;
            }
            __syncthreads();
        }
    }

    // ---------------- GEMM1: H = Xg @ Wslice^T, K = 2048, 3-stage PF=2 ----------------
    float acc[2][2][4];
    #pragma unroll
    for (int mf = 0; mf < 2; mf++)
        #pragma unroll
        for (int nf = 0; nf < 2; nf++)
            #pragma unroll
            for (int k = 0; k < 4; k++) acc[mf][nf][k] = 0.f;

    const int wf  = tid >> 3;
    const int gf  = (wf < 16) ? (e1*16 + wf) : (e2*16 + wf - 16);
    const int wc4 = tid & 7;
    const float* wsrc = g_W1c + (size_t)gf * DIM + wc4*4;

    auto loadStage = [&](int s){
        int st = (s % 3);
        int kb = s * 32;
        #pragma unroll
        for (int i = 0; i < 4; i++){
            int q = tid + i*256; int row = q >> 3; int c4 = q & 7;
            cp16(&Xs[st*XSTG + row*PAD + c4*4],
                 x + (size_t)idx[row]*DIM + kb + c4*4);
        }
        cp16(&Ws[st*WSTG + wf*PAD + wc4*4], wsrc + kb);
        cp_commit();
    };

    loadStage(0); loadStage(1);

    for (int s = 0; s < 64; s++){
        if (s < 63) cp_wait<1>();
        else        cp_wait<0>();
        __syncthreads();
        if (s + 2 < 64) loadStage(s + 2);

        const float* Ab = Xs + (s % 3)*XSTG + mw*32*PAD;
        const float* Wb = Ws + (s % 3)*WSTG + nw*16*PAD;
        #pragma unroll
        for (int ks = 0; ks < 4; ks++){
            int kc = ks * 8;
            uint32_t a[2][4];
            #pragma unroll
            for (int mf = 0; mf < 2; mf++){
                a[mf][0] = f2tf(Ab[(mf*16 +     g)*PAD + kc + t4]);
                a[mf][1] = f2tf(Ab[(mf*16 + 8 + g)*PAD + kc + t4]);
                a[mf][2] = f2tf(Ab[(mf*16 +     g)*PAD + kc + t4 + 4]);
                a[mf][3] = f2tf(Ab[(mf*16 + 8 + g)*PAD + kc + t4 + 4]);
            }
            #pragma unroll
            for (int nf = 0; nf < 2; nf++){
                uint32_t b[2];
                b[0] = __float_as_uint(Wb[(nf*8 + g)*PAD + kc + t4]);
                b[1] = __float_as_uint(Wb[(nf*8 + g)*PAD + kc + t4 + 4]);
                #pragma unroll
                for (int mf = 0; mf < 2; mf++) mma8(acc[mf][nf], a[mf], b);
            }
        }
    }
    __syncthreads();

    // ---- epilogue 1: H' = tf32(gelu(H)) -> Hs ----
    #pragma unroll
    for (int mf = 0; mf < 2; mf++){
        int r0 = mw*32 + mf*16 + g;
        #pragma unroll
        for (int nf = 0; nf < 2; nf++){
            int c0 = nw*16 + nf*8 + 2*t4;
            Hs[r0*PAD + c0]       = rndtf(gelu_exact(acc[mf][nf][0]));
            Hs[r0*PAD + c0 + 1]   = rndtf(gelu_exact(acc[mf][nf][1]));
            Hs[(r0+8)*PAD + c0]   = rndtf(gelu_exact(acc[mf][nf][2]));
            Hs[(r0+8)*PAD + c0+1] = rndtf(gelu_exact(acc[mf][nf][3]));
        }
    }
    __syncthreads();

    // ------ GEMM2: out = H' @ [B_e1;B_e2]^T, K=32, 32 chunks of 64 dims ------
    // H' fragments are chunk-invariant: hoist them into registers ONCE.
    uint32_t ha[4][2][4];
    {
        const float* Hb = Hs + mw*32*PAD;
        #pragma unroll
        for (int ks = 0; ks < 4; ks++){
            int kc = ks * 8;
            #pragma unroll
            for (int mf = 0; mf < 2; mf++){
                ha[ks][mf][0] = __float_as_uint(Hb[(mf*16 +     g)*PAD + kc + t4]);
                ha[ks][mf][1] = __float_as_uint(Hb[(mf*16 + 8 + g)*PAD + kc + t4]);
                ha[ks][mf][2] = __float_as_uint(Hb[(mf*16 +     g)*PAD + kc + t4 + 4]);
                ha[ks][mf][3] = __float_as_uint(Hb[(mf*16 + 8 + g)*PAD + kc + t4 + 4]);
            }
        }
    }

    auto loadB = [&](int c){
        int buf = c & 1;
        int dBase = c * 64;
        #pragma unroll
        for (int i = 0; i < 2; i++){
            int q = tid + i*256;
            int d = q >> 3; int j4 = q & 7;
            const float* src = (j4 < 4)
                ? g_B2 + ((size_t)e1*DIM + dBase + d)*RANK + j4*4
                : g_B2 + ((size_t)e2*DIM + dBase + d)*RANK + (j4-4)*4;
            cp16(&Bs[buf*64*PAD + d*PAD + j4*4], src);
        }
        cp_commit();
    };

    loadB(0);

    for (int c = 0; c < 32; c++){
        if (c + 1 < 32){ loadB(c + 1); cp_wait<1>(); }
        else           { cp_wait<0>(); }
        __syncthreads();

        float acc2[2][4][4];
        #pragma unroll
        for (int mf = 0; mf < 2; mf++)
            #pragma unroll
            for (int nf = 0; nf < 4; nf++)
                #pragma unroll
                for (int k = 0; k < 4; k++) acc2[mf][nf][k] = 0.f;

        const float* Bb = Bs + (c & 1)*64*PAD + nw*32*PAD;
        #pragma unroll
        for (int ks = 0; ks < 4; ks++){
            int kc = ks * 8;
            #pragma unroll
            for (int nf = 0; nf < 4; nf++){
                uint32_t b[2];
                b[0] = __float_as_uint(Bb[(nf*8 + g)*PAD + kc + t4]);
                b[1] = __float_as_uint(Bb[(nf*8 + g)*PAD + kc + t4 + 4]);
                #pragma unroll
                for (int mf = 0; mf < 2; mf++) mma8(acc2[mf][nf], ha[ks][mf], b);
            }
        }

        int dBase = c * 64;
        #pragma unroll
        for (int mf = 0; mf < 2; mf++){
            int ra = mw*32 + mf*16 + g;
            int rb = ra + 8;
            size_t toka = (size_t)idx[ra]*DIM;
            size_t tokb = (size_t)idx[rb]*DIM;
            #pragma unroll
            for (int nf = 0; nf < 4; nf++){
                int c0 = dBase + nw*32 + nf*8 + 2*t4;
                if (ra < len)
                    *reinterpret_cast<float2*>(&out[toka + c0]) =
                        make_float2(acc2[mf][nf][0], acc2[mf][nf][1]);
                if (rb < len)
                    *reinterpret_cast<float2*>(&out[tokb + c0]) =
                        make_float2(acc2[mf][nf][2], acc2[mf][nf][3]);
            }
        }
        __syncthreads();
    }
}

// ============================ launch ============================
extern "C" void kernel_launch(void* const* d_in, const int* in_sizes, int n_in,
                              void* d_out, int out_size)
{
    const float* x  = (const float*)d_in[0];
    const float* gW = (const float*)d_in[1];
    const float* gb = (const float*)d_in[2];
    const float* A  = (const float*)d_in[3];
    const float* Bm = (const float*)d_in[4];

    float* out = (float*)d_out;
    float* probs = out + (size_t)TOKENS * DIM;
    if (out_size < TOKENS*DIM + TOKENS*NEXP){
        void* p = nullptr;
        cudaGetSymbolAddress(&p, g_probs_fallback);
        probs = (float*)p;
    }

    size_t gate_smem  = (size_t)NEXP * DIM * sizeof(float);   // 64KB
    size_t fused_smem = (size_t)(3*XSTG + 3*WSTG + 128*PAD + 2*64*PAD) * sizeof(float)
                      + 128 * sizeof(int);
    cudaFuncSetAttribute(gate_kernel, cudaFuncAttributeMaxDynamicSharedMemorySize,
                         (int)gate_smem);
    cudaFuncSetAttribute(fused_kernel, cudaFuncAttributeMaxDynamicSharedMemorySize,
                         (int)fused_smem);

    pack_kernel<<<(2*NFEAT*DIM + 511)/512, 512>>>(Bm, A);
    gate_kernel<<<512, 512, gate_smem>>>(x, gW, gb, probs);
    fused_kernel<<<NTMAX, 256, fused_smem>>>(x, out);
}